// round 1
// baseline (speedup 1.0000x reference)
#include <cuda_runtime.h>
#include <cuda_bf16.h>

#define DIMC 1024
#define NHEAD 16
#define HDIM 64
#define BB 4
#define TT 2048
#define MROWS (BB * TT)   // 8192

// Scratch (device globals — allocation-free contract)
__device__ float g_q[BB * NHEAD * TT * HDIM];   // [B,H,T,D]
__device__ float g_k[BB * NHEAD * TT * HDIM];
__device__ float g_v[BB * NHEAD * TT * HDIM];
__device__ float g_att[MROWS * DIMC];           // [B*T, C] attention output

// ---------------------------------------------------------------------------
// GEMM: C[M,N] = A[M,K] @ W[N,K]^T  (both row-major, K contiguous)
// BM=BN=64, BK=16, 256 threads, 4x4 register tile per thread.
// qkv_mode=1: scatter store into [B,H,T,D] (one head per N-tile since BN=64).
// blockIdx.z selects (W, D) among three.
// ---------------------------------------------------------------------------
__global__ __launch_bounds__(256) void gemm_kernel(
    const float* __restrict__ A,
    const float* __restrict__ W0, const float* __restrict__ W1,
    const float* __restrict__ W2,
    float* __restrict__ D0, float* __restrict__ D1, float* __restrict__ D2,
    int qkv_mode)
{
    __shared__ float As[16][68];
    __shared__ float Bs[16][68];

    const float* W = W0;
    float* D = D0;
    if (blockIdx.z == 1) { W = W1; D = D1; }
    else if (blockIdx.z == 2) { W = W2; D = D2; }

    const int tid = threadIdx.x;
    const int tx = tid & 15;     // N group
    const int ty = tid >> 4;     // M group
    const int r0 = blockIdx.y * 64;
    const int c0 = blockIdx.x * 64;

    // load indexing: each thread loads one float4 of A and one of W per K-tile
    const int lm = tid >> 2;          // 0..63 (row within tile)
    const int lk = (tid & 3) * 4;     // 0,4,8,12 (k within tile)
    const float* Arow = A + (size_t)(r0 + lm) * DIMC + lk;
    const float* Wrow = W + (size_t)(c0 + lm) * DIMC + lk;

    float acc[4][4];
#pragma unroll
    for (int i = 0; i < 4; i++)
#pragma unroll
        for (int j = 0; j < 4; j++) acc[i][j] = 0.f;

    for (int k0 = 0; k0 < DIMC; k0 += 16) {
        float4 a4 = *(const float4*)(Arow + k0);
        float4 b4 = *(const float4*)(Wrow + k0);
        __syncthreads();
        As[lk + 0][lm] = a4.x; As[lk + 1][lm] = a4.y;
        As[lk + 2][lm] = a4.z; As[lk + 3][lm] = a4.w;
        Bs[lk + 0][lm] = b4.x; Bs[lk + 1][lm] = b4.y;
        Bs[lk + 2][lm] = b4.z; Bs[lk + 3][lm] = b4.w;
        __syncthreads();
#pragma unroll
        for (int k = 0; k < 16; k++) {
            float4 av = *(const float4*)&As[k][ty * 4];
            float4 bv = *(const float4*)&Bs[k][tx * 4];
            float ar[4] = {av.x, av.y, av.z, av.w};
            float br[4] = {bv.x, bv.y, bv.z, bv.w};
#pragma unroll
            for (int i = 0; i < 4; i++)
#pragma unroll
                for (int j = 0; j < 4; j++)
                    acc[i][j] += ar[i] * br[j];
        }
    }

    if (!qkv_mode) {
#pragma unroll
        for (int i = 0; i < 4; i++) {
            int row = r0 + ty * 4 + i;
            float4 o = make_float4(acc[i][0], acc[i][1], acc[i][2], acc[i][3]);
            *(float4*)(D + (size_t)row * DIMC + c0 + tx * 4) = o;
        }
    } else {
        // c0 == h*64 exactly (BN == HDIM, gridDim.x == NHEAD)
        int h = blockIdx.x;
#pragma unroll
        for (int i = 0; i < 4; i++) {
            int row = r0 + ty * 4 + i;
            int b = row >> 11;          // /2048
            int t = row & 2047;
            float4 o = make_float4(acc[i][0], acc[i][1], acc[i][2], acc[i][3]);
            size_t idx = (((size_t)(b * NHEAD + h) * TT + t) * HDIM) + tx * 4;
            *(float4*)(D + idx) = o;
        }
    }
}

// ---------------------------------------------------------------------------
// Flash attention (causal). One block = 64 query rows of one (b,h).
// BQ=64, BK=32, D=64, 256 threads. Online softmax, O in registers.
// Writes directly into g_att with [B*T, C] layout (c = h*64 + d).
// ---------------------------------------------------------------------------
__global__ __launch_bounds__(256) void attn_kernel()
{
    __shared__ float Qst[64][68];   // [d][r]  (transposed Q)
    __shared__ float Kst[64][36];   // [d][k]  (transposed K)
    __shared__ float Vs[32][68];    // [k][d]
    __shared__ float Ps[64][33];    // scores / probs
    __shared__ float alp[64];
    __shared__ float lrow[64];

    const int tid = threadIdx.x;
    const int bh  = blockIdx.y;          // b*16 + h
    const int q0  = blockIdx.x * 64;

    const float* Q = g_q + (size_t)bh * TT * HDIM;
    const float* K = g_k + (size_t)bh * TT * HDIM;
    const float* V = g_v + (size_t)bh * TT * HDIM;

    // Load Q tile transposed: 64 rows x 64 dims
#pragma unroll
    for (int it = 0; it < 4; it++) {
        int e = tid + it * 256;
        int r = e >> 4;
        int dq = (e & 15) * 4;
        float4 v4 = *(const float4*)(Q + (size_t)(q0 + r) * HDIM + dq);
        Qst[dq + 0][r] = v4.x; Qst[dq + 1][r] = v4.y;
        Qst[dq + 2][r] = v4.z; Qst[dq + 3][r] = v4.w;
    }

    const int rq = tid >> 2;          // O row (0..63)
    const int ds = (tid & 3) * 16;    // O dim base
    const int ty = tid >> 4;          // S row group (0..15) -> rows ty*4..
    const int tx = tid & 15;          // S col group -> cols tx*2..

    float O[16];
#pragma unroll
    for (int u = 0; u < 16; u++) O[u] = 0.f;
    float m_i = -1e30f, l_i = 0.f;    // valid for tid < 64

    const float scale = 0.125f;       // 1/sqrt(64)
    const int ntiles = (q0 >> 5) + 2;

    for (int kt = 0; kt < ntiles; kt++) {
        const int k0 = kt * 32;
        __syncthreads();
        // Load K (transposed) + V tiles: 32 rows x 64 dims each
#pragma unroll
        for (int it = 0; it < 2; it++) {
            int e = tid + it * 256;
            int k = e >> 4;
            int dq = (e & 15) * 4;
            float4 kv = *(const float4*)(K + (size_t)(k0 + k) * HDIM + dq);
            Kst[dq + 0][k] = kv.x; Kst[dq + 1][k] = kv.y;
            Kst[dq + 2][k] = kv.z; Kst[dq + 3][k] = kv.w;
            float4 vv = *(const float4*)(V + (size_t)(k0 + k) * HDIM + dq);
            *(float4*)&Vs[k][dq] = vv;
        }
        __syncthreads();

        // S = Q @ K^T : each thread 4 rows x 2 cols
        float sacc[4][2];
#pragma unroll
        for (int i = 0; i < 4; i++) { sacc[i][0] = 0.f; sacc[i][1] = 0.f; }
#pragma unroll 8
        for (int d = 0; d < 64; d++) {
            float4 qa = *(const float4*)&Qst[d][ty * 4];
            float2 kb = *(const float2*)&Kst[d][tx * 2];
            float qr[4] = {qa.x, qa.y, qa.z, qa.w};
#pragma unroll
            for (int i = 0; i < 4; i++) {
                sacc[i][0] += qr[i] * kb.x;
                sacc[i][1] += qr[i] * kb.y;
            }
        }

        const bool need_mask = (k0 + 32 > q0);
#pragma unroll
        for (int i = 0; i < 4; i++) {
#pragma unroll
            for (int j = 0; j < 2; j++) {
                int rr = ty * 4 + i;
                int kk = tx * 2 + j;
                float s = sacc[i][j] * scale;
                if (need_mask && (k0 + kk > q0 + rr)) s = -1e30f;
                Ps[rr][kk] = s;
            }
        }
        __syncthreads();

        // Online softmax: one thread per query row
        if (tid < 64) {
            float mx = m_i;
#pragma unroll
            for (int k = 0; k < 32; k++) mx = fmaxf(mx, Ps[tid][k]);
            float a = __expf(m_i - mx);
            float s = 0.f;
#pragma unroll
            for (int k = 0; k < 32; k++) {
                float p = __expf(Ps[tid][k] - mx);
                Ps[tid][k] = p;
                s += p;
            }
            l_i = l_i * a + s;
            m_i = mx;
            alp[tid] = a;
            lrow[tid] = l_i;
        }
        __syncthreads();

        // Rescale O and accumulate P @ V
        const float a = alp[rq];
#pragma unroll
        for (int u = 0; u < 16; u++) O[u] *= a;
#pragma unroll 8
        for (int k = 0; k < 32; k++) {
            float p = Ps[rq][k];
            const float4* vp = (const float4*)&Vs[k][ds];
            float4 v0 = vp[0], v1 = vp[1], v2 = vp[2], v3 = vp[3];
            O[0]  += p * v0.x; O[1]  += p * v0.y; O[2]  += p * v0.z; O[3]  += p * v0.w;
            O[4]  += p * v1.x; O[5]  += p * v1.y; O[6]  += p * v1.z; O[7]  += p * v1.w;
            O[8]  += p * v2.x; O[9]  += p * v2.y; O[10] += p * v2.z; O[11] += p * v2.w;
            O[12] += p * v3.x; O[13] += p * v3.y; O[14] += p * v3.z; O[15] += p * v3.w;
        }
    }

    // Final normalize + store to [B*T, C] layout
    const float linv = 1.0f / lrow[rq];
    const int b = bh >> 4;
    const int h = bh & 15;
    float* outp = g_att + ((size_t)(b * TT) + q0 + rq) * DIMC + h * HDIM + ds;
#pragma unroll
    for (int u = 0; u < 4; u++) {
        float4 o = make_float4(O[u * 4 + 0] * linv, O[u * 4 + 1] * linv,
                               O[u * 4 + 2] * linv, O[u * 4 + 3] * linv);
        *(float4*)(outp + u * 4) = o;
    }
}

// ---------------------------------------------------------------------------
extern "C" void kernel_launch(void* const* d_in, const int* in_sizes, int n_in,
                              void* d_out, int out_size)
{
    const float* x  = (const float*)d_in[0];
    // d_in[1] = mask (unused; causal applied analytically)
    const float* wq = (const float*)d_in[2];
    const float* wk = (const float*)d_in[3];
    const float* wv = (const float*)d_in[4];
    const float* wo = (const float*)d_in[5];
    float* out = (float*)d_out;

    float *dq, *dk, *dv, *datt;
    cudaGetSymbolAddress((void**)&dq,   g_q);
    cudaGetSymbolAddress((void**)&dk,   g_k);
    cudaGetSymbolAddress((void**)&dv,   g_v);
    cudaGetSymbolAddress((void**)&datt, g_att);

    // QKV projections: grid (N tiles=16, M tiles=128, 3 weights)
    gemm_kernel<<<dim3(16, 128, 3), 256>>>(x, wq, wk, wv, dq, dk, dv, 1);

    // Flash attention: grid (32 q-tiles, 64 b*h)
    attn_kernel<<<dim3(32, 64), 256>>>();

    // Output projection: plain store into d_out
    gemm_kernel<<<dim3(16, 128, 1), 256>>>(datt, wo, wo, wo, out, out, out, 0);
}

// round 2
// speedup vs baseline: 1.6061x; 1.6061x over previous
#include <cuda_runtime.h>
#include <cuda_bf16.h>

#define DIMC 1024
#define NHEAD 16
#define HDIM 64
#define BB 4
#define TT 2048
#define MROWS (BB * TT)   // 8192

// Scratch (device globals — allocation-free contract)
__device__ float g_q[BB * NHEAD * TT * HDIM];   // [B,H,T,D]
__device__ float g_k[BB * NHEAD * TT * HDIM];
__device__ float g_v[BB * NHEAD * TT * HDIM];
__device__ float g_att[MROWS * DIMC];           // [B*T, C] attention output

// ---------------------------------------------------------------------------
// GEMM: C[M,N] = A[M,K] @ W[N,K]^T. 128x128 block tile, BK=8, 256 threads,
// 8x8 register tile, double-buffered shared. qkv_mode scatters to [B,H,T,D].
// ---------------------------------------------------------------------------
__global__ __launch_bounds__(256, 2) void gemm_kernel(
    const float* __restrict__ A,
    const float* __restrict__ W0, const float* __restrict__ W1,
    const float* __restrict__ W2,
    float* __restrict__ D0, float* __restrict__ D1, float* __restrict__ D2,
    int qkv_mode)
{
    __shared__ float As[2][8][132];
    __shared__ float Bs[2][8][132];

    const float* W = W0;
    float* D = D0;
    if (blockIdx.z == 1) { W = W1; D = D1; }
    else if (blockIdx.z == 2) { W = W2; D = D2; }

    const int tid = threadIdx.x;
    const int tx = tid & 15;     // N group
    const int ty = tid >> 4;     // M group
    const int r0 = blockIdx.y * 128;
    const int c0 = blockIdx.x * 128;

    const int lrow = tid >> 1;           // 0..127
    const int lk   = (tid & 1) * 4;      // 0 or 4
    const float* Ap = A + (size_t)(r0 + lrow) * DIMC + lk;
    const float* Wp = W + (size_t)(c0 + lrow) * DIMC + lk;

    float acc[8][8];
#pragma unroll
    for (int i = 0; i < 8; i++)
#pragma unroll
        for (int j = 0; j < 8; j++) acc[i][j] = 0.f;

    // prologue: load tile 0
    {
        float4 a4 = *(const float4*)(Ap);
        float4 b4 = *(const float4*)(Wp);
        As[0][lk + 0][lrow] = a4.x; As[0][lk + 1][lrow] = a4.y;
        As[0][lk + 2][lrow] = a4.z; As[0][lk + 3][lrow] = a4.w;
        Bs[0][lk + 0][lrow] = b4.x; Bs[0][lk + 1][lrow] = b4.y;
        Bs[0][lk + 2][lrow] = b4.z; Bs[0][lk + 3][lrow] = b4.w;
    }
    __syncthreads();

    int buf = 0;
    for (int kt = 1; kt < DIMC / 8; kt++) {
        float4 na = *(const float4*)(Ap + kt * 8);
        float4 nb = *(const float4*)(Wp + kt * 8);

#pragma unroll
        for (int k = 0; k < 8; k++) {
            float4 a0 = *(const float4*)&As[buf][k][ty * 4];
            float4 a1 = *(const float4*)&As[buf][k][ty * 4 + 64];
            float4 b0 = *(const float4*)&Bs[buf][k][tx * 4];
            float4 b1 = *(const float4*)&Bs[buf][k][tx * 4 + 64];
            float ar[8] = {a0.x, a0.y, a0.z, a0.w, a1.x, a1.y, a1.z, a1.w};
            float br[8] = {b0.x, b0.y, b0.z, b0.w, b1.x, b1.y, b1.z, b1.w};
#pragma unroll
            for (int i = 0; i < 8; i++)
#pragma unroll
                for (int j = 0; j < 8; j++)
                    acc[i][j] += ar[i] * br[j];
        }

        int nb_ = buf ^ 1;
        As[nb_][lk + 0][lrow] = na.x; As[nb_][lk + 1][lrow] = na.y;
        As[nb_][lk + 2][lrow] = na.z; As[nb_][lk + 3][lrow] = na.w;
        Bs[nb_][lk + 0][lrow] = nb.x; Bs[nb_][lk + 1][lrow] = nb.y;
        Bs[nb_][lk + 2][lrow] = nb.z; Bs[nb_][lk + 3][lrow] = nb.w;
        __syncthreads();
        buf ^= 1;
    }

    // final tile
#pragma unroll
    for (int k = 0; k < 8; k++) {
        float4 a0 = *(const float4*)&As[buf][k][ty * 4];
        float4 a1 = *(const float4*)&As[buf][k][ty * 4 + 64];
        float4 b0 = *(const float4*)&Bs[buf][k][tx * 4];
        float4 b1 = *(const float4*)&Bs[buf][k][tx * 4 + 64];
        float ar[8] = {a0.x, a0.y, a0.z, a0.w, a1.x, a1.y, a1.z, a1.w};
        float br[8] = {b0.x, b0.y, b0.z, b0.w, b1.x, b1.y, b1.z, b1.w};
#pragma unroll
        for (int i = 0; i < 8; i++)
#pragma unroll
            for (int j = 0; j < 8; j++)
                acc[i][j] += ar[i] * br[j];
    }

    // store
    if (!qkv_mode) {
#pragma unroll
        for (int ih = 0; ih < 2; ih++)
#pragma unroll
        for (int i = 0; i < 4; i++) {
            int row = r0 + ih * 64 + ty * 4 + i;
            int ii = ih * 4 + i;
#pragma unroll
            for (int jh = 0; jh < 2; jh++) {
                float4 o = make_float4(acc[ii][jh*4+0], acc[ii][jh*4+1],
                                       acc[ii][jh*4+2], acc[ii][jh*4+3]);
                *(float4*)(D + (size_t)row * DIMC + c0 + jh * 64 + tx * 4) = o;
            }
        }
    } else {
#pragma unroll
        for (int ih = 0; ih < 2; ih++)
#pragma unroll
        for (int i = 0; i < 4; i++) {
            int row = r0 + ih * 64 + ty * 4 + i;
            int ii = ih * 4 + i;
            int b = row >> 11;
            int t = row & 2047;
#pragma unroll
            for (int jh = 0; jh < 2; jh++) {
                int h = blockIdx.x * 2 + jh;     // BN=128 = 2 heads
                float4 o = make_float4(acc[ii][jh*4+0], acc[ii][jh*4+1],
                                       acc[ii][jh*4+2], acc[ii][jh*4+3]);
                size_t idx = (((size_t)(b * NHEAD + h) * TT + t) * HDIM) + tx * 4;
                *(float4*)(D + idx) = o;
            }
        }
    }
}

// ---------------------------------------------------------------------------
// Flash attention (causal). BQ=128, BK=64, 256 threads, dynamic smem.
// S: 16x16 thread grid, 8 rows x 4 cols each. Online softmax in registers
// with 16-lane shuffle reductions. PV: 2 threads/row, 32 dims each.
// ---------------------------------------------------------------------------
#define QST(d, r) Qst[(d) * 132 + (r)]
#define KST(d, k) Kst[(d) * 68 + (k)]
#define VSM(k, d) Vs[(k) * 68 + (d)]
#define PSM(r, k) Ps[(r) * 68 + (k)]

#define ATTN_SMEM_FLOATS (64*132 + 64*68 + 64*68 + 128*68 + 128 + 128)

__global__ __launch_bounds__(256, 2) void attn_kernel()
{
    extern __shared__ float sm[];
    float* Qst = sm;                       // [64][132] (d-major, transposed)
    float* Kst = Qst + 64 * 132;           // [64][68]  (d-major, transposed)
    float* Vs  = Kst + 64 * 68;            // [64][68]  (k-major)
    float* Ps  = Vs  + 64 * 68;            // [128][68]
    float* alp = Ps  + 128 * 68;           // [128]
    float* lrw = alp + 128;                // [128]

    const int tid = threadIdx.x;
    const int bh  = blockIdx.y;            // b*16 + h
    const int q0  = blockIdx.x * 128;

    const float* Q = g_q + (size_t)bh * TT * HDIM;
    const float* K = g_k + (size_t)bh * TT * HDIM;
    const float* V = g_v + (size_t)bh * TT * HDIM;

    // Load Q tile transposed: 128 rows x 64 dims
#pragma unroll
    for (int it = 0; it < 8; it++) {
        int e = tid + it * 256;
        int r = e >> 4;
        int dq = (e & 15) * 4;
        float4 v4 = *(const float4*)(Q + (size_t)(q0 + r) * HDIM + dq);
        QST(dq + 0, r) = v4.x; QST(dq + 1, r) = v4.y;
        QST(dq + 2, r) = v4.z; QST(dq + 3, r) = v4.w;
    }

    const int ty = tid >> 4;          // S rows ty*8 .. ty*8+7
    const int tx = tid & 15;          // S cols tx*4 .. tx*4+3
    const int rq = tid >> 1;          // PV row (0..127)
    const int dbase = (tid & 1) * 32; // PV dim base

    float O[32];
#pragma unroll
    for (int u = 0; u < 32; u++) O[u] = 0.f;
    float m_i[8], l_i[8];
#pragma unroll
    for (int i = 0; i < 8; i++) { m_i[i] = -1e30f; l_i[i] = 0.f; }

    const float scale = 0.125f;       // 1/sqrt(64)
    const int ntiles = (q0 >> 6) + 2;

    for (int kt = 0; kt < ntiles; kt++) {
        const int k0 = kt * 64;
        __syncthreads();   // prev PV reads of Vs/Ps done

        // Load K (transposed) + V tiles: 64 rows x 64 dims each
#pragma unroll
        for (int it = 0; it < 4; it++) {
            int e = tid + it * 256;
            int k = e >> 4;
            int dq = (e & 15) * 4;
            float4 kv = *(const float4*)(K + (size_t)(k0 + k) * HDIM + dq);
            KST(dq + 0, k) = kv.x; KST(dq + 1, k) = kv.y;
            KST(dq + 2, k) = kv.z; KST(dq + 3, k) = kv.w;
            float4 vv = *(const float4*)(V + (size_t)(k0 + k) * HDIM + dq);
            *(float4*)&VSM(k, dq) = vv;
        }
        __syncthreads();

        // S = Q @ K^T : 8 rows x 4 cols per thread
        float sacc[8][4];
#pragma unroll
        for (int i = 0; i < 8; i++)
#pragma unroll
            for (int j = 0; j < 4; j++) sacc[i][j] = 0.f;

#pragma unroll 8
        for (int d = 0; d < 64; d++) {
            float4 qa0 = *(const float4*)&QST(d, ty * 8);
            float4 qa1 = *(const float4*)&QST(d, ty * 8 + 4);
            float4 kb  = *(const float4*)&KST(d, tx * 4);
            float qr[8] = {qa0.x, qa0.y, qa0.z, qa0.w,
                           qa1.x, qa1.y, qa1.z, qa1.w};
            float kr[4] = {kb.x, kb.y, kb.z, kb.w};
#pragma unroll
            for (int i = 0; i < 8; i++)
#pragma unroll
                for (int j = 0; j < 4; j++)
                    sacc[i][j] += qr[i] * kr[j];
        }

        // Online softmax (registers + 16-lane shuffles)
        const bool need_mask = (k0 + 63 > q0);
#pragma unroll
        for (int i = 0; i < 8; i++) {
            const int rr = ty * 8 + i;
            const int grow = q0 + rr;
            float mx = -1e30f;
#pragma unroll
            for (int j = 0; j < 4; j++) {
                float s = sacc[i][j] * scale;
                if (need_mask && (k0 + tx * 4 + j > grow)) s = -1e30f;
                sacc[i][j] = s;
                mx = fmaxf(mx, s);
            }
#pragma unroll
            for (int m = 8; m >= 1; m >>= 1)
                mx = fmaxf(mx, __shfl_xor_sync(0xffffffffu, mx, m));
            float mnew = fmaxf(m_i[i], mx);
            float alpha = __expf(m_i[i] - mnew);
            float rs = 0.f;
#pragma unroll
            for (int j = 0; j < 4; j++) {
                float p = __expf(sacc[i][j] - mnew);
                sacc[i][j] = p;
                rs += p;
            }
#pragma unroll
            for (int m = 8; m >= 1; m >>= 1)
                rs += __shfl_xor_sync(0xffffffffu, rs, m);
            l_i[i] = l_i[i] * alpha + rs;
            m_i[i] = mnew;
            if (tx == 0) { alp[rr] = alpha; lrw[rr] = l_i[i]; }
            *(float4*)&PSM(rr, tx * 4) =
                make_float4(sacc[i][0], sacc[i][1], sacc[i][2], sacc[i][3]);
        }
        __syncthreads();   // Ps/alp visible

        // O rescale + P @ V
        const float a = alp[rq];
#pragma unroll
        for (int u = 0; u < 32; u++) O[u] *= a;
#pragma unroll 4
        for (int k = 0; k < 64; k++) {
            float p = PSM(rq, k);
            const float4* vp = (const float4*)&VSM(k, dbase);
#pragma unroll
            for (int u = 0; u < 8; u++) {
                float4 v = vp[u];
                O[u * 4 + 0] += p * v.x;
                O[u * 4 + 1] += p * v.y;
                O[u * 4 + 2] += p * v.z;
                O[u * 4 + 3] += p * v.w;
            }
        }
    }

    // Final normalize + store to [B*T, C] layout
    const float linv = 1.0f / lrw[rq];
    const int b = bh >> 4;
    const int h = bh & 15;
    float* outp = g_att + ((size_t)(b * TT) + q0 + rq) * DIMC + h * HDIM + dbase;
#pragma unroll
    for (int u = 0; u < 8; u++) {
        float4 o = make_float4(O[u * 4 + 0] * linv, O[u * 4 + 1] * linv,
                               O[u * 4 + 2] * linv, O[u * 4 + 3] * linv);
        *(float4*)(outp + u * 4) = o;
    }
}

// ---------------------------------------------------------------------------
extern "C" void kernel_launch(void* const* d_in, const int* in_sizes, int n_in,
                              void* d_out, int out_size)
{
    const float* x  = (const float*)d_in[0];
    // d_in[1] = mask (unused; causal applied analytically)
    const float* wq = (const float*)d_in[2];
    const float* wk = (const float*)d_in[3];
    const float* wv = (const float*)d_in[4];
    const float* wo = (const float*)d_in[5];
    float* out = (float*)d_out;

    float *dq, *dk, *dv, *datt;
    cudaGetSymbolAddress((void**)&dq,   g_q);
    cudaGetSymbolAddress((void**)&dk,   g_k);
    cudaGetSymbolAddress((void**)&dv,   g_v);
    cudaGetSymbolAddress((void**)&datt, g_att);

    size_t attn_smem = ATTN_SMEM_FLOATS * sizeof(float);
    cudaFuncSetAttribute(attn_kernel,
                         cudaFuncAttributeMaxDynamicSharedMemorySize,
                         (int)attn_smem);

    // QKV projections: 128x128 tiles, grid (8, 64, 3)
    gemm_kernel<<<dim3(8, 64, 3), 256>>>(x, wq, wk, wv, dq, dk, dv, 1);

    // Flash attention: grid (16 q-tiles, 64 b*h)
    attn_kernel<<<dim3(16, 64), 256, attn_smem>>>();

    // Output projection
    gemm_kernel<<<dim3(8, 64, 1), 256>>>(datt, wo, wo, wo, out, out, out, 0);
}

// round 3
// speedup vs baseline: 1.9866x; 1.2369x over previous
#include <cuda_runtime.h>
#include <cuda_bf16.h>

#define DIMC 1024
#define NHEAD 16
#define HDIM 64
#define BB 4
#define TT 2048
#define MROWS (BB * TT)   // 8192

// Scratch (device globals — allocation-free contract)
__device__ float g_q[BB * NHEAD * TT * HDIM];   // [B,H,T,D]
__device__ float g_k[BB * NHEAD * TT * HDIM];
__device__ float g_v[BB * NHEAD * TT * HDIM];
__device__ float g_att[MROWS * DIMC];           // [B*T, C] attention output

// ---------------------------------------------------------------------------
// GEMM: C[M,N] = A[M,K] @ W[N,K]^T. 128x128 block tile, BK=8, 256 threads,
// 8x8 register tile, double-buffered shared. qkv_mode scatters to [B,H,T,D].
// ---------------------------------------------------------------------------
__global__ __launch_bounds__(256, 2) void gemm_kernel(
    const float* __restrict__ A,
    const float* __restrict__ W0, const float* __restrict__ W1,
    const float* __restrict__ W2,
    float* __restrict__ D0, float* __restrict__ D1, float* __restrict__ D2,
    int qkv_mode)
{
    __shared__ float As[2][8][132];
    __shared__ float Bs[2][8][132];

    const float* W = W0;
    float* D = D0;
    if (blockIdx.z == 1) { W = W1; D = D1; }
    else if (blockIdx.z == 2) { W = W2; D = D2; }

    const int tid = threadIdx.x;
    const int tx = tid & 15;     // N group
    const int ty = tid >> 4;     // M group
    const int r0 = blockIdx.y * 128;
    const int c0 = blockIdx.x * 128;

    const int lrow = tid >> 1;           // 0..127
    const int lk   = (tid & 1) * 4;      // 0 or 4
    const float* Ap = A + (size_t)(r0 + lrow) * DIMC + lk;
    const float* Wp = W + (size_t)(c0 + lrow) * DIMC + lk;

    float acc[8][8];
#pragma unroll
    for (int i = 0; i < 8; i++)
#pragma unroll
        for (int j = 0; j < 8; j++) acc[i][j] = 0.f;

    // prologue: load tile 0
    {
        float4 a4 = *(const float4*)(Ap);
        float4 b4 = *(const float4*)(Wp);
        As[0][lk + 0][lrow] = a4.x; As[0][lk + 1][lrow] = a4.y;
        As[0][lk + 2][lrow] = a4.z; As[0][lk + 3][lrow] = a4.w;
        Bs[0][lk + 0][lrow] = b4.x; Bs[0][lk + 1][lrow] = b4.y;
        Bs[0][lk + 2][lrow] = b4.z; Bs[0][lk + 3][lrow] = b4.w;
    }
    __syncthreads();

    int buf = 0;
    for (int kt = 1; kt < DIMC / 8; kt++) {
        float4 na = *(const float4*)(Ap + kt * 8);
        float4 nb = *(const float4*)(Wp + kt * 8);

#pragma unroll
        for (int k = 0; k < 8; k++) {
            float4 a0 = *(const float4*)&As[buf][k][ty * 4];
            float4 a1 = *(const float4*)&As[buf][k][ty * 4 + 64];
            float4 b0 = *(const float4*)&Bs[buf][k][tx * 4];
            float4 b1 = *(const float4*)&Bs[buf][k][tx * 4 + 64];
            float ar[8] = {a0.x, a0.y, a0.z, a0.w, a1.x, a1.y, a1.z, a1.w};
            float br[8] = {b0.x, b0.y, b0.z, b0.w, b1.x, b1.y, b1.z, b1.w};
#pragma unroll
            for (int i = 0; i < 8; i++)
#pragma unroll
                for (int j = 0; j < 8; j++)
                    acc[i][j] += ar[i] * br[j];
        }

        int nb_ = buf ^ 1;
        As[nb_][lk + 0][lrow] = na.x; As[nb_][lk + 1][lrow] = na.y;
        As[nb_][lk + 2][lrow] = na.z; As[nb_][lk + 3][lrow] = na.w;
        Bs[nb_][lk + 0][lrow] = nb.x; Bs[nb_][lk + 1][lrow] = nb.y;
        Bs[nb_][lk + 2][lrow] = nb.z; Bs[nb_][lk + 3][lrow] = nb.w;
        __syncthreads();
        buf ^= 1;
    }

    // final tile
#pragma unroll
    for (int k = 0; k < 8; k++) {
        float4 a0 = *(const float4*)&As[buf][k][ty * 4];
        float4 a1 = *(const float4*)&As[buf][k][ty * 4 + 64];
        float4 b0 = *(const float4*)&Bs[buf][k][tx * 4];
        float4 b1 = *(const float4*)&Bs[buf][k][tx * 4 + 64];
        float ar[8] = {a0.x, a0.y, a0.z, a0.w, a1.x, a1.y, a1.z, a1.w};
        float br[8] = {b0.x, b0.y, b0.z, b0.w, b1.x, b1.y, b1.z, b1.w};
#pragma unroll
        for (int i = 0; i < 8; i++)
#pragma unroll
            for (int j = 0; j < 8; j++)
                acc[i][j] += ar[i] * br[j];
    }

    // store
    if (!qkv_mode) {
#pragma unroll
        for (int ih = 0; ih < 2; ih++)
#pragma unroll
        for (int i = 0; i < 4; i++) {
            int row = r0 + ih * 64 + ty * 4 + i;
            int ii = ih * 4 + i;
#pragma unroll
            for (int jh = 0; jh < 2; jh++) {
                float4 o = make_float4(acc[ii][jh*4+0], acc[ii][jh*4+1],
                                       acc[ii][jh*4+2], acc[ii][jh*4+3]);
                *(float4*)(D + (size_t)row * DIMC + c0 + jh * 64 + tx * 4) = o;
            }
        }
    } else {
#pragma unroll
        for (int ih = 0; ih < 2; ih++)
#pragma unroll
        for (int i = 0; i < 4; i++) {
            int row = r0 + ih * 64 + ty * 4 + i;
            int ii = ih * 4 + i;
            int b = row >> 11;
            int t = row & 2047;
#pragma unroll
            for (int jh = 0; jh < 2; jh++) {
                int h = blockIdx.x * 2 + jh;     // BN=128 = 2 heads
                float4 o = make_float4(acc[ii][jh*4+0], acc[ii][jh*4+1],
                                       acc[ii][jh*4+2], acc[ii][jh*4+3]);
                size_t idx = (((size_t)(b * NHEAD + h) * TT + t) * HDIM) + tx * 4;
                *(float4*)(D + idx) = o;
            }
        }
    }
}

// ---------------------------------------------------------------------------
// Flash attention (causal). BQ=128, BK=64, 256 threads, dynamic smem.
// Thread (ty,tx) owns rows ty*8..+7 and (for both S and O) cols tx*4..+3.
// Softmax state (m, l, alpha) fully register-resident; PV is an 8x4
// outer-product GEMM with float4 smem loads (1.5 B/FMA).
// ---------------------------------------------------------------------------
#define QST(d, r) Qst[(d) * 132 + (r)]
#define KST(d, k) Kst[(d) * 68 + (k)]
#define VSM(k, d) Vs[(k) * 68 + (d)]
#define PSM(r, k) Ps[(r) * 68 + (k)]

#define ATTN_SMEM_FLOATS (64*132 + 64*68 + 64*68 + 128*68)

__global__ __launch_bounds__(256) void attn_kernel()
{
    extern __shared__ float sm[];
    float* Qst = sm;                       // [64][132] (d-major, transposed)
    float* Kst = Qst + 64 * 132;           // [64][68]  (d-major, transposed)
    float* Vs  = Kst + 64 * 68;            // [64][68]  (k-major)
    float* Ps  = Vs  + 64 * 68;            // [128][68]

    const int tid = threadIdx.x;
    const int bh  = blockIdx.y;                          // b*16 + h
    const int q0  = (gridDim.x - 1 - blockIdx.x) * 128;  // heavy tiles first

    const float* Q = g_q + (size_t)bh * TT * HDIM;
    const float* K = g_k + (size_t)bh * TT * HDIM;
    const float* V = g_v + (size_t)bh * TT * HDIM;

    // Load Q tile transposed: 128 rows x 64 dims
#pragma unroll
    for (int it = 0; it < 8; it++) {
        int e = tid + it * 256;
        int r = e >> 4;
        int dq = (e & 15) * 4;
        float4 v4 = *(const float4*)(Q + (size_t)(q0 + r) * HDIM + dq);
        QST(dq + 0, r) = v4.x; QST(dq + 1, r) = v4.y;
        QST(dq + 2, r) = v4.z; QST(dq + 3, r) = v4.w;
    }

    const int ty = tid >> 4;          // rows ty*8 .. ty*8+7
    const int tx = tid & 15;          // cols tx*4 .. tx*4+3

    float O[8][4];
#pragma unroll
    for (int i = 0; i < 8; i++)
#pragma unroll
        for (int j = 0; j < 4; j++) O[i][j] = 0.f;
    float m_i[8], l_i[8];
#pragma unroll
    for (int i = 0; i < 8; i++) { m_i[i] = -1e30f; l_i[i] = 0.f; }

    const float scale = 0.125f;       // 1/sqrt(64)
    const int ntiles = (q0 >> 6) + 2;

    for (int kt = 0; kt < ntiles; kt++) {
        const int k0 = kt * 64;
        __syncthreads();   // prev PV reads of Vs/Ps done

        // Load K (transposed) + V tiles: 64 rows x 64 dims each
#pragma unroll
        for (int it = 0; it < 4; it++) {
            int e = tid + it * 256;
            int k = e >> 4;
            int dq = (e & 15) * 4;
            float4 kv = *(const float4*)(K + (size_t)(k0 + k) * HDIM + dq);
            KST(dq + 0, k) = kv.x; KST(dq + 1, k) = kv.y;
            KST(dq + 2, k) = kv.z; KST(dq + 3, k) = kv.w;
            float4 vv = *(const float4*)(V + (size_t)(k0 + k) * HDIM + dq);
            *(float4*)&VSM(k, dq) = vv;
        }
        __syncthreads();

        // S = Q @ K^T : 8 rows x 4 cols per thread
        float sacc[8][4];
#pragma unroll
        for (int i = 0; i < 8; i++)
#pragma unroll
            for (int j = 0; j < 4; j++) sacc[i][j] = 0.f;

#pragma unroll 8
        for (int d = 0; d < 64; d++) {
            float4 qa0 = *(const float4*)&QST(d, ty * 8);
            float4 qa1 = *(const float4*)&QST(d, ty * 8 + 4);
            float4 kb  = *(const float4*)&KST(d, tx * 4);
            float qr[8] = {qa0.x, qa0.y, qa0.z, qa0.w,
                           qa1.x, qa1.y, qa1.z, qa1.w};
            float kr[4] = {kb.x, kb.y, kb.z, kb.w};
#pragma unroll
            for (int i = 0; i < 8; i++)
#pragma unroll
                for (int j = 0; j < 4; j++)
                    sacc[i][j] += qr[i] * kr[j];
        }

        // Online softmax (registers + 16-lane shuffles), rescale O in place.
        const bool need_mask = (k0 + 63 > q0);
#pragma unroll
        for (int i = 0; i < 8; i++) {
            const int rr = ty * 8 + i;
            const int grow = q0 + rr;
            float mx = -1e30f;
#pragma unroll
            for (int j = 0; j < 4; j++) {
                float s = sacc[i][j] * scale;
                if (need_mask && (k0 + tx * 4 + j > grow)) s = -1e30f;
                sacc[i][j] = s;
                mx = fmaxf(mx, s);
            }
#pragma unroll
            for (int m = 8; m >= 1; m >>= 1)
                mx = fmaxf(mx, __shfl_xor_sync(0xffffffffu, mx, m));
            float mnew = fmaxf(m_i[i], mx);
            float alpha = __expf(m_i[i] - mnew);
            float rs = 0.f;
#pragma unroll
            for (int j = 0; j < 4; j++) {
                float p = __expf(sacc[i][j] - mnew);
                sacc[i][j] = p;
                rs += p;
            }
#pragma unroll
            for (int m = 8; m >= 1; m >>= 1)
                rs += __shfl_xor_sync(0xffffffffu, rs, m);
            l_i[i] = l_i[i] * alpha + rs;
            m_i[i] = mnew;
#pragma unroll
            for (int j = 0; j < 4; j++) O[i][j] *= alpha;
            *(float4*)&PSM(rr, tx * 4) =
                make_float4(sacc[i][0], sacc[i][1], sacc[i][2], sacc[i][3]);
        }
        __syncthreads();   // Ps visible

        // O += P @ V : 8x4 outer-product tile, k in chunks of 4
#pragma unroll 4
        for (int k = 0; k < 64; k += 4) {
            float4 p4[8];
#pragma unroll
            for (int i = 0; i < 8; i++)
                p4[i] = *(const float4*)&PSM(ty * 8 + i, k);
            float4 v4[4];
#pragma unroll
            for (int c = 0; c < 4; c++)
                v4[c] = *(const float4*)&VSM(k + c, tx * 4);
#pragma unroll
            for (int i = 0; i < 8; i++) {
                float pr[4] = {p4[i].x, p4[i].y, p4[i].z, p4[i].w};
#pragma unroll
                for (int c = 0; c < 4; c++) {
                    O[i][0] += pr[c] * v4[c].x;
                    O[i][1] += pr[c] * v4[c].y;
                    O[i][2] += pr[c] * v4[c].z;
                    O[i][3] += pr[c] * v4[c].w;
                }
            }
        }
    }

    // Final normalize + store to [B*T, C] layout
    const int b = bh >> 4;
    const int h = bh & 15;
#pragma unroll
    for (int i = 0; i < 8; i++) {
        const float linv = 1.0f / l_i[i];
        int row = q0 + ty * 8 + i;
        float* outp = g_att + ((size_t)(b * TT) + row) * DIMC + h * HDIM + tx * 4;
        float4 o = make_float4(O[i][0] * linv, O[i][1] * linv,
                               O[i][2] * linv, O[i][3] * linv);
        *(float4*)outp = o;
    }
}

// ---------------------------------------------------------------------------
extern "C" void kernel_launch(void* const* d_in, const int* in_sizes, int n_in,
                              void* d_out, int out_size)
{
    const float* x  = (const float*)d_in[0];
    // d_in[1] = mask (unused; causal applied analytically)
    const float* wq = (const float*)d_in[2];
    const float* wk = (const float*)d_in[3];
    const float* wv = (const float*)d_in[4];
    const float* wo = (const float*)d_in[5];
    float* out = (float*)d_out;

    float *dq, *dk, *dv, *datt;
    cudaGetSymbolAddress((void**)&dq,   g_q);
    cudaGetSymbolAddress((void**)&dk,   g_k);
    cudaGetSymbolAddress((void**)&dv,   g_v);
    cudaGetSymbolAddress((void**)&datt, g_att);

    size_t attn_smem = ATTN_SMEM_FLOATS * sizeof(float);
    cudaFuncSetAttribute(attn_kernel,
                         cudaFuncAttributeMaxDynamicSharedMemorySize,
                         (int)attn_smem);

    // QKV projections: 128x128 tiles, grid (8, 64, 3)
    gemm_kernel<<<dim3(8, 64, 3), 256>>>(x, wq, wk, wv, dq, dk, dv, 1);

    // Flash attention: grid (16 q-tiles, 64 b*h)
    attn_kernel<<<dim3(16, 64), 256, attn_smem>>>();

    // Output projection
    gemm_kernel<<<dim3(8, 64, 1), 256>>>(datt, wo, wo, wo, out, out, out, 0);
}

// round 4
// speedup vs baseline: 2.8180x; 1.4185x over previous
#include <cuda_runtime.h>
#include <cuda_bf16.h>

#define DIMC 1024
#define NHEAD 16
#define HDIM 64
#define BB 4
#define TT 2048
#define MROWS (BB * TT)   // 8192

// Scratch (device globals — allocation-free contract)
__device__ float g_q[BB * NHEAD * TT * HDIM];   // [B,H,T,D]
__device__ float g_k[BB * NHEAD * TT * HDIM];
__device__ float g_v[BB * NHEAD * TT * HDIM];
__device__ float g_att[MROWS * DIMC];           // [B*T, C] attention output

__device__ __forceinline__ unsigned f2tf32(float x) {
    unsigned u;
    asm("cvt.rna.tf32.f32 %0, %1;" : "=r"(u) : "f"(x));
    return u;
}

#define MMA_TF32(d, a, b)                                                    \
    asm volatile("mma.sync.aligned.m16n8k8.row.col.f32.tf32.tf32.f32 "        \
                 "{%0,%1,%2,%3}, {%4,%5,%6,%7}, {%8,%9}, {%0,%1,%2,%3};"      \
                 : "+f"(d[0]), "+f"(d[1]), "+f"(d[2]), "+f"(d[3])             \
                 : "r"(a[0]), "r"(a[1]), "r"(a[2]), "r"(a[3]),                \
                   "r"(b[0]), "r"(b[1]))

// ---------------------------------------------------------------------------
// TF32 tensor-core GEMM: C[M,N] = A[M,K] @ W[N,K]^T.
// 128x128 block tile, BK=8, 256 threads (8 warps in 2x4 grid, 64x32/warp),
// m16n8k8 mma atoms, k-major smem (stride 136 => conflict-free frag loads),
// double-buffered. qkv_mode scatters to [B,H,T,D].
// ---------------------------------------------------------------------------
#define KSTRIDE 136

__global__ __launch_bounds__(256, 2) void gemm_kernel(
    const float* __restrict__ A,
    const float* __restrict__ W0, const float* __restrict__ W1,
    const float* __restrict__ W2,
    float* __restrict__ D0, float* __restrict__ D1, float* __restrict__ D2,
    int qkv_mode)
{
    __shared__ unsigned As[2][8][KSTRIDE];
    __shared__ unsigned Bs[2][8][KSTRIDE];

    const float* W = W0;
    float* D = D0;
    if (blockIdx.z == 1) { W = W1; D = D1; }
    else if (blockIdx.z == 2) { W = W2; D = D2; }

    const int tid  = threadIdx.x;
    const int lane = tid & 31;
    const int w    = tid >> 5;
    const int wm   = w >> 2;          // 0..1  (m: 64 rows each)
    const int wn   = w & 3;           // 0..3  (n: 32 cols each)
    const int r0 = blockIdx.y * 128;
    const int c0 = blockIdx.x * 128;

    const int lrow = tid >> 1;           // 0..127
    const int lk   = (tid & 1) * 4;      // 0 or 4
    const float* Ap = A + (size_t)(r0 + lrow) * DIMC + lk;
    const float* Wp = W + (size_t)(c0 + lrow) * DIMC + lk;

    const int fr = lane >> 2;            // 0..7  (row within atom / n within atom)
    const int fc = lane & 3;             // 0..3  (k within atom)

    float acc[4][4][4];
#pragma unroll
    for (int mi = 0; mi < 4; mi++)
#pragma unroll
        for (int ni = 0; ni < 4; ni++)
#pragma unroll
            for (int e = 0; e < 4; e++) acc[mi][ni][e] = 0.f;

    // prologue: stage tile 0 (tf32-rounded)
    {
        float4 a4 = *(const float4*)(Ap);
        float4 b4 = *(const float4*)(Wp);
        As[0][lk + 0][lrow] = f2tf32(a4.x); As[0][lk + 1][lrow] = f2tf32(a4.y);
        As[0][lk + 2][lrow] = f2tf32(a4.z); As[0][lk + 3][lrow] = f2tf32(a4.w);
        Bs[0][lk + 0][lrow] = f2tf32(b4.x); Bs[0][lk + 1][lrow] = f2tf32(b4.y);
        Bs[0][lk + 2][lrow] = f2tf32(b4.z); Bs[0][lk + 3][lrow] = f2tf32(b4.w);
    }
    __syncthreads();

    int buf = 0;
    for (int kt = 1; kt <= DIMC / 8; kt++) {
        float4 na, nb;
        const bool more = (kt < DIMC / 8);
        if (more) {
            na = *(const float4*)(Ap + kt * 8);
            nb = *(const float4*)(Wp + kt * 8);
        }

        // load fragments
        unsigned af[4][4], bfr[4][2];
#pragma unroll
        for (int mi = 0; mi < 4; mi++) {
            int r = wm * 64 + mi * 16 + fr;
            af[mi][0] = As[buf][fc][r];
            af[mi][1] = As[buf][fc][r + 8];
            af[mi][2] = As[buf][fc + 4][r];
            af[mi][3] = As[buf][fc + 4][r + 8];
        }
#pragma unroll
        for (int ni = 0; ni < 4; ni++) {
            int n = wn * 32 + ni * 8 + fr;
            bfr[ni][0] = Bs[buf][fc][n];
            bfr[ni][1] = Bs[buf][fc + 4][n];
        }
#pragma unroll
        for (int mi = 0; mi < 4; mi++)
#pragma unroll
            for (int ni = 0; ni < 4; ni++)
                MMA_TF32(acc[mi][ni], af[mi], bfr[ni]);

        if (more) {
            int nb_ = buf ^ 1;
            As[nb_][lk + 0][lrow] = f2tf32(na.x); As[nb_][lk + 1][lrow] = f2tf32(na.y);
            As[nb_][lk + 2][lrow] = f2tf32(na.z); As[nb_][lk + 3][lrow] = f2tf32(na.w);
            Bs[nb_][lk + 0][lrow] = f2tf32(nb.x); Bs[nb_][lk + 1][lrow] = f2tf32(nb.y);
            Bs[nb_][lk + 2][lrow] = f2tf32(nb.z); Bs[nb_][lk + 3][lrow] = f2tf32(nb.w);
            __syncthreads();
            buf ^= 1;
        }
    }

    // epilogue
    if (!qkv_mode) {
#pragma unroll
        for (int mi = 0; mi < 4; mi++) {
            int r = r0 + wm * 64 + mi * 16 + fr;
#pragma unroll
            for (int ni = 0; ni < 4; ni++) {
                int c = c0 + wn * 32 + ni * 8 + fc * 2;
                *(float2*)(D + (size_t)r * DIMC + c) =
                    make_float2(acc[mi][ni][0], acc[mi][ni][1]);
                *(float2*)(D + (size_t)(r + 8) * DIMC + c) =
                    make_float2(acc[mi][ni][2], acc[mi][ni][3]);
            }
        }
    } else {
#pragma unroll
        for (int mi = 0; mi < 4; mi++) {
            int row = r0 + wm * 64 + mi * 16 + fr;
#pragma unroll
            for (int half = 0; half < 2; half++) {
                int rr = row + half * 8;
                int b = rr >> 11;
                int t = rr & 2047;
#pragma unroll
                for (int ni = 0; ni < 4; ni++) {
                    int cc = wn * 32 + ni * 8 + fc * 2;       // 0..127
                    int h = blockIdx.x * 2 + (cc >> 6);
                    int d = cc & 63;
                    size_t idx = (((size_t)(b * NHEAD + h) * TT + t) * HDIM) + d;
                    *(float2*)(D0 == D ? D + idx : D + idx) =  // D already selected
                        make_float2(acc[mi][ni][half * 2 + 0],
                                    acc[mi][ni][half * 2 + 1]);
                }
            }
        }
    }
}

// ---------------------------------------------------------------------------
// Flash attention (causal). BQ=128, BK=64, 256 threads, dynamic smem.
// Thread (ty,tx) owns rows ty*8..+7 and cols tx*4..+3 for both S and O.
// Register-resident online softmax; PV as 8x4 outer-product GEMM.
// ---------------------------------------------------------------------------
#define QST(d, r) Qst[(d) * 132 + (r)]
#define KST(d, k) Kst[(d) * 68 + (k)]
#define VSM(k, d) Vs[(k) * 68 + (d)]
#define PSM(r, k) Ps[(r) * 68 + (k)]

#define ATTN_SMEM_FLOATS (64*132 + 64*68 + 64*68 + 128*68)

__global__ __launch_bounds__(256) void attn_kernel()
{
    extern __shared__ float sm[];
    float* Qst = sm;                       // [64][132] (d-major, transposed)
    float* Kst = Qst + 64 * 132;           // [64][68]  (d-major, transposed)
    float* Vs  = Kst + 64 * 68;            // [64][68]  (k-major)
    float* Ps  = Vs  + 64 * 68;            // [128][68]

    const int tid = threadIdx.x;
    const int bh  = blockIdx.y;                          // b*16 + h
    const int q0  = (gridDim.x - 1 - blockIdx.x) * 128;  // heavy tiles first

    const float* Q = g_q + (size_t)bh * TT * HDIM;
    const float* K = g_k + (size_t)bh * TT * HDIM;
    const float* V = g_v + (size_t)bh * TT * HDIM;

    // Load Q tile transposed: 128 rows x 64 dims
#pragma unroll
    for (int it = 0; it < 8; it++) {
        int e = tid + it * 256;
        int r = e >> 4;
        int dq = (e & 15) * 4;
        float4 v4 = *(const float4*)(Q + (size_t)(q0 + r) * HDIM + dq);
        QST(dq + 0, r) = v4.x; QST(dq + 1, r) = v4.y;
        QST(dq + 2, r) = v4.z; QST(dq + 3, r) = v4.w;
    }

    const int ty = tid >> 4;          // rows ty*8 .. ty*8+7
    const int tx = tid & 15;          // cols tx*4 .. tx*4+3

    float O[8][4];
#pragma unroll
    for (int i = 0; i < 8; i++)
#pragma unroll
        for (int j = 0; j < 4; j++) O[i][j] = 0.f;
    float m_i[8], l_i[8];
#pragma unroll
    for (int i = 0; i < 8; i++) { m_i[i] = -1e30f; l_i[i] = 0.f; }

    const float scale = 0.125f;       // 1/sqrt(64)
    const int ntiles = (q0 >> 6) + 2;

    for (int kt = 0; kt < ntiles; kt++) {
        const int k0 = kt * 64;
        __syncthreads();   // prev PV reads of Vs/Ps done

        // Load K (transposed) + V tiles: 64 rows x 64 dims each
#pragma unroll
        for (int it = 0; it < 4; it++) {
            int e = tid + it * 256;
            int k = e >> 4;
            int dq = (e & 15) * 4;
            float4 kv = *(const float4*)(K + (size_t)(k0 + k) * HDIM + dq);
            KST(dq + 0, k) = kv.x; KST(dq + 1, k) = kv.y;
            KST(dq + 2, k) = kv.z; KST(dq + 3, k) = kv.w;
            float4 vv = *(const float4*)(V + (size_t)(k0 + k) * HDIM + dq);
            *(float4*)&VSM(k, dq) = vv;
        }
        __syncthreads();

        // S = Q @ K^T : 8 rows x 4 cols per thread
        float sacc[8][4];
#pragma unroll
        for (int i = 0; i < 8; i++)
#pragma unroll
            for (int j = 0; j < 4; j++) sacc[i][j] = 0.f;

#pragma unroll 8
        for (int d = 0; d < 64; d++) {
            float4 qa0 = *(const float4*)&QST(d, ty * 8);
            float4 qa1 = *(const float4*)&QST(d, ty * 8 + 4);
            float4 kb  = *(const float4*)&KST(d, tx * 4);
            float qr[8] = {qa0.x, qa0.y, qa0.z, qa0.w,
                           qa1.x, qa1.y, qa1.z, qa1.w};
            float kr[4] = {kb.x, kb.y, kb.z, kb.w};
#pragma unroll
            for (int i = 0; i < 8; i++)
#pragma unroll
                for (int j = 0; j < 4; j++)
                    sacc[i][j] += qr[i] * kr[j];
        }

        // Online softmax (registers + 16-lane shuffles), rescale O in place.
        const bool need_mask = (k0 + 63 > q0);
#pragma unroll
        for (int i = 0; i < 8; i++) {
            const int rr = ty * 8 + i;
            const int grow = q0 + rr;
            float mx = -1e30f;
#pragma unroll
            for (int j = 0; j < 4; j++) {
                float s = sacc[i][j] * scale;
                if (need_mask && (k0 + tx * 4 + j > grow)) s = -1e30f;
                sacc[i][j] = s;
                mx = fmaxf(mx, s);
            }
#pragma unroll
            for (int m = 8; m >= 1; m >>= 1)
                mx = fmaxf(mx, __shfl_xor_sync(0xffffffffu, mx, m));
            float mnew = fmaxf(m_i[i], mx);
            float alpha = __expf(m_i[i] - mnew);
            float rs = 0.f;
#pragma unroll
            for (int j = 0; j < 4; j++) {
                float p = __expf(sacc[i][j] - mnew);
                sacc[i][j] = p;
                rs += p;
            }
#pragma unroll
            for (int m = 8; m >= 1; m >>= 1)
                rs += __shfl_xor_sync(0xffffffffu, rs, m);
            l_i[i] = l_i[i] * alpha + rs;
            m_i[i] = mnew;
#pragma unroll
            for (int j = 0; j < 4; j++) O[i][j] *= alpha;
            *(float4*)&PSM(rr, tx * 4) =
                make_float4(sacc[i][0], sacc[i][1], sacc[i][2], sacc[i][3]);
        }
        __syncthreads();   // Ps visible

        // O += P @ V : 8x4 outer-product tile, k in chunks of 4
#pragma unroll 4
        for (int k = 0; k < 64; k += 4) {
            float4 p4[8];
#pragma unroll
            for (int i = 0; i < 8; i++)
                p4[i] = *(const float4*)&PSM(ty * 8 + i, k);
            float4 v4[4];
#pragma unroll
            for (int c = 0; c < 4; c++)
                v4[c] = *(const float4*)&VSM(k + c, tx * 4);
#pragma unroll
            for (int i = 0; i < 8; i++) {
                float pr[4] = {p4[i].x, p4[i].y, p4[i].z, p4[i].w};
#pragma unroll
                for (int c = 0; c < 4; c++) {
                    O[i][0] += pr[c] * v4[c].x;
                    O[i][1] += pr[c] * v4[c].y;
                    O[i][2] += pr[c] * v4[c].z;
                    O[i][3] += pr[c] * v4[c].w;
                }
            }
        }
    }

    // Final normalize + store to [B*T, C] layout
    const int b = bh >> 4;
    const int h = bh & 15;
#pragma unroll
    for (int i = 0; i < 8; i++) {
        const float linv = 1.0f / l_i[i];
        int row = q0 + ty * 8 + i;
        float* outp = g_att + ((size_t)(b * TT) + row) * DIMC + h * HDIM + tx * 4;
        float4 o = make_float4(O[i][0] * linv, O[i][1] * linv,
                               O[i][2] * linv, O[i][3] * linv);
        *(float4*)outp = o;
    }
}

// ---------------------------------------------------------------------------
extern "C" void kernel_launch(void* const* d_in, const int* in_sizes, int n_in,
                              void* d_out, int out_size)
{
    const float* x  = (const float*)d_in[0];
    // d_in[1] = mask (unused; causal applied analytically)
    const float* wq = (const float*)d_in[2];
    const float* wk = (const float*)d_in[3];
    const float* wv = (const float*)d_in[4];
    const float* wo = (const float*)d_in[5];
    float* out = (float*)d_out;

    float *dq, *dk, *dv, *datt;
    cudaGetSymbolAddress((void**)&dq,   g_q);
    cudaGetSymbolAddress((void**)&dk,   g_k);
    cudaGetSymbolAddress((void**)&dv,   g_v);
    cudaGetSymbolAddress((void**)&datt, g_att);

    size_t attn_smem = ATTN_SMEM_FLOATS * sizeof(float);
    cudaFuncSetAttribute(attn_kernel,
                         cudaFuncAttributeMaxDynamicSharedMemorySize,
                         (int)attn_smem);

    // QKV projections: 128x128 tiles, grid (8, 64, 3)
    gemm_kernel<<<dim3(8, 64, 3), 256>>>(x, wq, wk, wv, dq, dk, dv, 1);

    // Flash attention: grid (16 q-tiles, 64 b*h)
    attn_kernel<<<dim3(16, 64), 256, attn_smem>>>();

    // Output projection
    gemm_kernel<<<dim3(8, 64, 1), 256>>>(datt, wo, wo, wo, out, out, out, 0);
}

// round 5
// speedup vs baseline: 3.9557x; 1.4037x over previous
#include <cuda_runtime.h>
#include <cuda_bf16.h>

#define DIMC 1024
#define NHEAD 16
#define HDIM 64
#define BB 4
#define TT 2048
#define MROWS (BB * TT)   // 8192

// Scratch (device globals — allocation-free contract)
__device__ float g_q[BB * NHEAD * TT * HDIM];   // [B,H,T,D]
__device__ float g_k[BB * NHEAD * TT * HDIM];
__device__ float g_v[BB * NHEAD * TT * HDIM];
__device__ float g_att[MROWS * DIMC];           // [B*T, C] attention output

__device__ __forceinline__ unsigned f2tf32(float x) {
    unsigned u;
    asm("cvt.rna.tf32.f32 %0, %1;" : "=r"(u) : "f"(x));
    return u;
}

// 2^x on the FMA/ALU pipes (no MUFU). x <= 0 expected; clamped at -120.
__device__ __forceinline__ float exp2_fast(float x) {
    x = fmaxf(x, -120.f);
    float n = floorf(x);
    float f = x - n;                 // [0,1)
    float p = 1.78656e-4f;           // ~(ln2)^6/720
    p = fmaf(p, f, 1.33336e-3f);
    p = fmaf(p, f, 9.61813e-3f);
    p = fmaf(p, f, 5.55041e-2f);
    p = fmaf(p, f, 2.40226507e-1f);
    p = fmaf(p, f, 6.93147181e-1f);
    p = fmaf(p, f, 1.0f);
    return __uint_as_float(__float_as_uint(p) + (((int)n) << 23));
}

#define MMA_TF32(d, a, b)                                                    \
    asm volatile("mma.sync.aligned.m16n8k8.row.col.f32.tf32.tf32.f32 "        \
                 "{%0,%1,%2,%3}, {%4,%5,%6,%7}, {%8,%9}, {%0,%1,%2,%3};"      \
                 : "+f"(d[0]), "+f"(d[1]), "+f"(d[2]), "+f"(d[3])             \
                 : "r"(a[0]), "r"(a[1]), "r"(a[2]), "r"(a[3]),                \
                   "r"(b[0]), "r"(b[1]))

// ---------------------------------------------------------------------------
// TF32 tensor-core GEMM: C[M,N] = A[M,K] @ W[N,K]^T.  (unchanged from R4)
// ---------------------------------------------------------------------------
#define KSTRIDE 136

__global__ __launch_bounds__(256, 2) void gemm_kernel(
    const float* __restrict__ A,
    const float* __restrict__ W0, const float* __restrict__ W1,
    const float* __restrict__ W2,
    float* __restrict__ D0, float* __restrict__ D1, float* __restrict__ D2,
    int qkv_mode)
{
    __shared__ unsigned As[2][8][KSTRIDE];
    __shared__ unsigned Bs[2][8][KSTRIDE];

    const float* W = W0;
    float* D = D0;
    if (blockIdx.z == 1) { W = W1; D = D1; }
    else if (blockIdx.z == 2) { W = W2; D = D2; }

    const int tid  = threadIdx.x;
    const int lane = tid & 31;
    const int w    = tid >> 5;
    const int wm   = w >> 2;
    const int wn   = w & 3;
    const int r0 = blockIdx.y * 128;
    const int c0 = blockIdx.x * 128;

    const int lrow = tid >> 1;
    const int lk   = (tid & 1) * 4;
    const float* Ap = A + (size_t)(r0 + lrow) * DIMC + lk;
    const float* Wp = W + (size_t)(c0 + lrow) * DIMC + lk;

    const int fr = lane >> 2;
    const int fc = lane & 3;

    float acc[4][4][4];
#pragma unroll
    for (int mi = 0; mi < 4; mi++)
#pragma unroll
        for (int ni = 0; ni < 4; ni++)
#pragma unroll
            for (int e = 0; e < 4; e++) acc[mi][ni][e] = 0.f;

    {
        float4 a4 = *(const float4*)(Ap);
        float4 b4 = *(const float4*)(Wp);
        As[0][lk + 0][lrow] = f2tf32(a4.x); As[0][lk + 1][lrow] = f2tf32(a4.y);
        As[0][lk + 2][lrow] = f2tf32(a4.z); As[0][lk + 3][lrow] = f2tf32(a4.w);
        Bs[0][lk + 0][lrow] = f2tf32(b4.x); Bs[0][lk + 1][lrow] = f2tf32(b4.y);
        Bs[0][lk + 2][lrow] = f2tf32(b4.z); Bs[0][lk + 3][lrow] = f2tf32(b4.w);
    }
    __syncthreads();

    int buf = 0;
    for (int kt = 1; kt <= DIMC / 8; kt++) {
        float4 na, nb;
        const bool more = (kt < DIMC / 8);
        if (more) {
            na = *(const float4*)(Ap + kt * 8);
            nb = *(const float4*)(Wp + kt * 8);
        }

        unsigned af[4][4], bfr[4][2];
#pragma unroll
        for (int mi = 0; mi < 4; mi++) {
            int r = wm * 64 + mi * 16 + fr;
            af[mi][0] = As[buf][fc][r];
            af[mi][1] = As[buf][fc][r + 8];
            af[mi][2] = As[buf][fc + 4][r];
            af[mi][3] = As[buf][fc + 4][r + 8];
        }
#pragma unroll
        for (int ni = 0; ni < 4; ni++) {
            int n = wn * 32 + ni * 8 + fr;
            bfr[ni][0] = Bs[buf][fc][n];
            bfr[ni][1] = Bs[buf][fc + 4][n];
        }
#pragma unroll
        for (int mi = 0; mi < 4; mi++)
#pragma unroll
            for (int ni = 0; ni < 4; ni++)
                MMA_TF32(acc[mi][ni], af[mi], bfr[ni]);

        if (more) {
            int nb_ = buf ^ 1;
            As[nb_][lk + 0][lrow] = f2tf32(na.x); As[nb_][lk + 1][lrow] = f2tf32(na.y);
            As[nb_][lk + 2][lrow] = f2tf32(na.z); As[nb_][lk + 3][lrow] = f2tf32(na.w);
            Bs[nb_][lk + 0][lrow] = f2tf32(nb.x); Bs[nb_][lk + 1][lrow] = f2tf32(nb.y);
            Bs[nb_][lk + 2][lrow] = f2tf32(nb.z); Bs[nb_][lk + 3][lrow] = f2tf32(nb.w);
            __syncthreads();
            buf ^= 1;
        }
    }

    if (!qkv_mode) {
#pragma unroll
        for (int mi = 0; mi < 4; mi++) {
            int r = r0 + wm * 64 + mi * 16 + fr;
#pragma unroll
            for (int ni = 0; ni < 4; ni++) {
                int c = c0 + wn * 32 + ni * 8 + fc * 2;
                *(float2*)(D + (size_t)r * DIMC + c) =
                    make_float2(acc[mi][ni][0], acc[mi][ni][1]);
                *(float2*)(D + (size_t)(r + 8) * DIMC + c) =
                    make_float2(acc[mi][ni][2], acc[mi][ni][3]);
            }
        }
    } else {
#pragma unroll
        for (int mi = 0; mi < 4; mi++) {
            int row = r0 + wm * 64 + mi * 16 + fr;
#pragma unroll
            for (int half = 0; half < 2; half++) {
                int rr = row + half * 8;
                int b = rr >> 11;
                int t = rr & 2047;
#pragma unroll
                for (int ni = 0; ni < 4; ni++) {
                    int cc = wn * 32 + ni * 8 + fc * 2;
                    int h = blockIdx.x * 2 + (cc >> 6);
                    int d = cc & 63;
                    size_t idx = (((size_t)(b * NHEAD + h) * TT + t) * HDIM) + d;
                    *(float2*)(D + idx) =
                        make_float2(acc[mi][ni][half * 2 + 0],
                                    acc[mi][ni][half * 2 + 1]);
                }
            }
        }
    }
}

// ---------------------------------------------------------------------------
// Flash attention, tensor-core edition. BQ=128, BK=64, 256 threads (8 warps,
// 4(m)x2(n)). S and PV via tf32 m16n8k8; online softmax in log2 domain with
// FMA-pipe exp2; P round-trips through smem as tf32.
// ---------------------------------------------------------------------------
#define ASTRIDE 68

__global__ __launch_bounds__(256, 1) void attn_kernel()
{
    extern __shared__ unsigned smu[];
    unsigned* Qs = smu;                    // [128][68] tf32, scaled by 0.125*log2e
    unsigned* Ks = Qs + 128 * ASTRIDE;     // [64][68]  tf32, natural [k][d]
    unsigned* Vt = Ks + 64 * ASTRIDE;      // [64][68]  tf32, transposed [d][k]
    unsigned* Ps = Vt + 64 * ASTRIDE;      // [128][68] tf32 probs
    float* red_max = (float*)(Ps + 128 * ASTRIDE);  // [2][128]
    float* red_sum = red_max + 2 * 128;             // [2][128]

    const int tid  = threadIdx.x;
    const int lane = tid & 31;
    const int w    = tid >> 5;
    const int wm   = w >> 1;          // 0..3 : rows wm*32..+31
    const int wn   = w & 1;           // 0..1 : cols wn*32..+31
    const int fr   = lane >> 2;
    const int fc   = lane & 3;

    const int bh = blockIdx.y;
    const int q0 = (gridDim.x - 1 - blockIdx.x) * 128;   // heavy tiles first

    const float* Q = g_q + (size_t)bh * TT * HDIM;
    const float* K = g_k + (size_t)bh * TT * HDIM;
    const float* V = g_v + (size_t)bh * TT * HDIM;

    const float qsc = 0.125f * 1.4426950408889634f;  // scale * log2(e)

    // Stage Q (tf32, scaled): 128 x 64
#pragma unroll
    for (int it = 0; it < 8; it++) {
        int e = tid + it * 256;
        int r = e >> 4, dq = (e & 15) * 4;
        float4 v4 = *(const float4*)(Q + (size_t)(q0 + r) * HDIM + dq);
        unsigned* p = &Qs[r * ASTRIDE + dq];
        p[0] = f2tf32(v4.x * qsc); p[1] = f2tf32(v4.y * qsc);
        p[2] = f2tf32(v4.z * qsc); p[3] = f2tf32(v4.w * qsc);
    }

    float O[2][4][4];
#pragma unroll
    for (int mi = 0; mi < 2; mi++)
#pragma unroll
        for (int ni = 0; ni < 4; ni++)
#pragma unroll
            for (int e = 0; e < 4; e++) O[mi][ni][e] = 0.f;
    float m_i[4], l_i[4];
#pragma unroll
    for (int s = 0; s < 4; s++) { m_i[s] = -1e30f; l_i[s] = 0.f; }

    const int ntiles = (q0 >> 6) + 2;

    for (int kt = 0; kt < ntiles; kt++) {
        const int k0 = kt * 64;
        __syncthreads();   // prev PV done before restaging

        // Stage K: Ks[k][d]
#pragma unroll
        for (int it = 0; it < 4; it++) {
            int e = tid + it * 256;
            int k = e >> 4, dq = (e & 15) * 4;
            float4 kv = *(const float4*)(K + (size_t)(k0 + k) * HDIM + dq);
            unsigned* p = &Ks[k * ASTRIDE + dq];
            p[0] = f2tf32(kv.x); p[1] = f2tf32(kv.y);
            p[2] = f2tf32(kv.z); p[3] = f2tf32(kv.w);
        }
        // Stage V transposed: Vt[d][k]
#pragma unroll
        for (int it = 0; it < 4; it++) {
            int e = tid + it * 256;
            int d = e & 63;
            int kq = (e >> 6) * 4;
            float v0 = V[(size_t)(k0 + kq + 0) * HDIM + d];
            float v1 = V[(size_t)(k0 + kq + 1) * HDIM + d];
            float v2 = V[(size_t)(k0 + kq + 2) * HDIM + d];
            float v3 = V[(size_t)(k0 + kq + 3) * HDIM + d];
            *(uint4*)&Vt[d * ASTRIDE + kq] =
                make_uint4(f2tf32(v0), f2tf32(v1), f2tf32(v2), f2tf32(v3));
        }
        __syncthreads();

        // S = Qs @ Ks^T (tf32 mma): per warp 32 rows x 32 cols
        float sacc[2][4][4];
#pragma unroll
        for (int mi = 0; mi < 2; mi++)
#pragma unroll
            for (int ni = 0; ni < 4; ni++)
#pragma unroll
                for (int e = 0; e < 4; e++) sacc[mi][ni][e] = 0.f;

#pragma unroll
        for (int kk = 0; kk < 8; kk++) {
            unsigned af[2][4];
#pragma unroll
            for (int mi = 0; mi < 2; mi++) {
                const unsigned* b = &Qs[(wm * 32 + mi * 16 + fr) * ASTRIDE + kk * 8 + fc];
                af[mi][0] = b[0];
                af[mi][1] = b[8 * ASTRIDE];
                af[mi][2] = b[4];
                af[mi][3] = b[8 * ASTRIDE + 4];
            }
            unsigned bf[4][2];
#pragma unroll
            for (int ni = 0; ni < 4; ni++) {
                const unsigned* b = &Ks[(wn * 32 + ni * 8 + fr) * ASTRIDE + kk * 8 + fc];
                bf[ni][0] = b[0];
                bf[ni][1] = b[4];
            }
#pragma unroll
            for (int mi = 0; mi < 2; mi++)
#pragma unroll
                for (int ni = 0; ni < 4; ni++)
                    MMA_TF32(sacc[mi][ni], af[mi], bf[ni]);
        }

        // Softmax part 1: mask + row max (log2 domain)
        const bool need_mask = (k0 + 63 > q0);
#pragma unroll
        for (int mi = 0; mi < 2; mi++)
#pragma unroll
        for (int h = 0; h < 2; h++) {
            int r = wm * 32 + mi * 16 + fr + h * 8;
            int rg = q0 + r;
            float rm = -1e30f;
#pragma unroll
            for (int ni = 0; ni < 4; ni++)
#pragma unroll
            for (int e = 0; e < 2; e++) {
                float s = sacc[mi][ni][h * 2 + e];
                if (need_mask && (k0 + wn * 32 + ni * 8 + fc * 2 + e > rg))
                    s = -1e30f;
                sacc[mi][ni][h * 2 + e] = s;
                rm = fmaxf(rm, s);
            }
            rm = fmaxf(rm, __shfl_xor_sync(0xffffffffu, rm, 1));
            rm = fmaxf(rm, __shfl_xor_sync(0xffffffffu, rm, 2));
            if (fc == 0) red_max[wn * 128 + r] = rm;
        }
        __syncthreads();

        // Softmax part 2: m/l/alpha, p = 2^(s - m), write P (tf32), rescale O
        float alpha_s[4];
#pragma unroll
        for (int mi = 0; mi < 2; mi++)
#pragma unroll
        for (int h = 0; h < 2; h++) {
            int slot = mi * 2 + h;
            int r = wm * 32 + mi * 16 + fr + h * 8;
            float tm = fmaxf(red_max[r], red_max[128 + r]);
            float mnew = fmaxf(m_i[slot], tm);
            float al = exp2_fast(m_i[slot] - mnew);
            m_i[slot] = mnew;
            alpha_s[slot] = al;
            float rs = 0.f;
#pragma unroll
            for (int ni = 0; ni < 4; ni++) {
                float p0 = exp2_fast(sacc[mi][ni][h * 2 + 0] - mnew);
                float p1 = exp2_fast(sacc[mi][ni][h * 2 + 1] - mnew);
                rs += p0 + p1;
                *(uint2*)&Ps[r * ASTRIDE + wn * 32 + ni * 8 + fc * 2] =
                    make_uint2(f2tf32(p0), f2tf32(p1));
            }
            rs += __shfl_xor_sync(0xffffffffu, rs, 1);
            rs += __shfl_xor_sync(0xffffffffu, rs, 2);
            if (fc == 0) red_sum[wn * 128 + r] = rs;
#pragma unroll
            for (int ni = 0; ni < 4; ni++) {
                O[mi][ni][h * 2 + 0] *= al;
                O[mi][ni][h * 2 + 1] *= al;
            }
        }
        __syncthreads();

        // l update
#pragma unroll
        for (int mi = 0; mi < 2; mi++)
#pragma unroll
        for (int h = 0; h < 2; h++) {
            int slot = mi * 2 + h;
            int r = wm * 32 + mi * 16 + fr + h * 8;
            l_i[slot] = l_i[slot] * alpha_s[slot] + red_sum[r] + red_sum[128 + r];
        }

        // O += P @ V (tf32 mma)
#pragma unroll
        for (int kk = 0; kk < 8; kk++) {
            unsigned af[2][4];
#pragma unroll
            for (int mi = 0; mi < 2; mi++) {
                const unsigned* b = &Ps[(wm * 32 + mi * 16 + fr) * ASTRIDE + kk * 8 + fc];
                af[mi][0] = b[0];
                af[mi][1] = b[8 * ASTRIDE];
                af[mi][2] = b[4];
                af[mi][3] = b[8 * ASTRIDE + 4];
            }
            unsigned bf[4][2];
#pragma unroll
            for (int ni = 0; ni < 4; ni++) {
                const unsigned* b = &Vt[(wn * 32 + ni * 8 + fr) * ASTRIDE + kk * 8 + fc];
                bf[ni][0] = b[0];
                bf[ni][1] = b[4];
            }
#pragma unroll
            for (int mi = 0; mi < 2; mi++)
#pragma unroll
                for (int ni = 0; ni < 4; ni++)
                    MMA_TF32(O[mi][ni], af[mi], bf[ni]);
        }
    }

    // Epilogue: normalize, store to [B*T, C]
    const int b = bh >> 4;
    const int h = bh & 15;
#pragma unroll
    for (int mi = 0; mi < 2; mi++)
#pragma unroll
    for (int hh = 0; hh < 2; hh++) {
        int slot = mi * 2 + hh;
        float linv = 1.0f / l_i[slot];
        int row = q0 + wm * 32 + mi * 16 + fr + hh * 8;
        float* op = g_att + ((size_t)(b * TT) + row) * DIMC + h * HDIM + wn * 32;
#pragma unroll
        for (int ni = 0; ni < 4; ni++) {
            *(float2*)(op + ni * 8 + fc * 2) =
                make_float2(O[mi][ni][hh * 2 + 0] * linv,
                            O[mi][ni][hh * 2 + 1] * linv);
        }
    }
}

#define ATTN_SMEM_BYTES ((128*ASTRIDE + 64*ASTRIDE + 64*ASTRIDE + 128*ASTRIDE) * 4 + 2 * 2 * 128 * 4)

// ---------------------------------------------------------------------------
extern "C" void kernel_launch(void* const* d_in, const int* in_sizes, int n_in,
                              void* d_out, int out_size)
{
    const float* x  = (const float*)d_in[0];
    // d_in[1] = mask (unused; causal applied analytically)
    const float* wq = (const float*)d_in[2];
    const float* wk = (const float*)d_in[3];
    const float* wv = (const float*)d_in[4];
    const float* wo = (const float*)d_in[5];
    float* out = (float*)d_out;

    float *dq, *dk, *dv, *datt;
    cudaGetSymbolAddress((void**)&dq,   g_q);
    cudaGetSymbolAddress((void**)&dk,   g_k);
    cudaGetSymbolAddress((void**)&dv,   g_v);
    cudaGetSymbolAddress((void**)&datt, g_att);

    cudaFuncSetAttribute(attn_kernel,
                         cudaFuncAttributeMaxDynamicSharedMemorySize,
                         ATTN_SMEM_BYTES);

    // QKV projections: 128x128 tiles, grid (8, 64, 3)
    gemm_kernel<<<dim3(8, 64, 3), 256>>>(x, wq, wk, wv, dq, dk, dv, 1);

    // Flash attention: grid (16 q-tiles, 64 b*h)
    attn_kernel<<<dim3(16, 64), 256, ATTN_SMEM_BYTES>>>();

    // Output projection
    gemm_kernel<<<dim3(8, 64, 1), 256>>>(datt, wo, wo, wo, out, out, out, 0);
}